// round 1
// baseline (speedup 1.0000x reference)
#include <cuda_runtime.h>
#include <cuda_bf16.h>
#include <cstddef>

#define NUM_CLASS 1000
#define DIMS      2048
#define HEADSZ    256
#define NSAMP     16384
#define ALPHA_F   0.999f

// Scratch (allocation-free rule: __device__ globals)
__device__ int    g_last_idx[NUM_CLASS];
__device__ double g_loss_accum;

// ---------------------------------------------------------------------------
// Kernel 0: reset per-call state (graph replays must be deterministic)
// ---------------------------------------------------------------------------
__global__ void ema_init_kernel() {
    int i = blockIdx.x * blockDim.x + threadIdx.x;
    if (i < NUM_CLASS) g_last_idx[i] = -1;
    if (i == 0)        g_loss_accum = 0.0;
}

// ---------------------------------------------------------------------------
// Kernel 1: per-sample SSE vs gathered center row, fused last-index atomicMax.
// One block per sample; 256 threads x 2 float4 = 2048 floats.
// ---------------------------------------------------------------------------
__global__ __launch_bounds__(256) void ema_loss_kernel(
    const float* __restrict__ x,
    const int*   __restrict__ labels,
    const float* __restrict__ centers)
{
    const int n   = blockIdx.x;
    const int lab = labels[n];

    if (threadIdx.x == 0) {
        atomicMax(&g_last_idx[lab], n);
    }

    const float4* __restrict__ xr = reinterpret_cast<const float4*>(x + (size_t)n * DIMS);
    const float4* __restrict__ cr = reinterpret_cast<const float4*>(centers + (size_t)lab * DIMS);

    float s = 0.0f;
#pragma unroll
    for (int i = 0; i < 2; ++i) {
        const int idx = threadIdx.x + i * 256;
        const float4 a = xr[idx];
        const float4 b = cr[idx];
        const float dx = a.x - b.x;
        const float dy = a.y - b.y;
        const float dz = a.z - b.z;
        const float dw = a.w - b.w;
        s += dx * dx + dy * dy + dz * dz + dw * dw;
    }

    // warp reduce
#pragma unroll
    for (int o = 16; o > 0; o >>= 1) s += __shfl_xor_sync(0xFFFFFFFFu, s, o);

    __shared__ float warp_s[8];
    if ((threadIdx.x & 31) == 0) warp_s[threadIdx.x >> 5] = s;
    __syncthreads();

    if (threadIdx.x < 8) {
        float v = warp_s[threadIdx.x];
#pragma unroll
        for (int o = 4; o > 0; o >>= 1) v += __shfl_xor_sync(0xFFu, v, o);
        if (threadIdx.x == 0) {
            atomicAdd(&g_loss_accum, (double)v);
        }
    }
}

// ---------------------------------------------------------------------------
// Kernel 2: EMA scatter update (last write wins) + loss finalize.
// One block per class; 256 threads x 8 floats = 2048.
// Scalar stores: output centers base may be 4B-aligned only (loss slot first).
// ---------------------------------------------------------------------------
__global__ __launch_bounds__(256) void ema_update_kernel(
    const float* __restrict__ x,
    const float* __restrict__ centers,
    float*       __restrict__ out_loss,      // may be null
    float*       __restrict__ out_centers)
{
    const int c    = blockIdx.x;
    const int last = g_last_idx[c];

    const float4* __restrict__ cr = reinterpret_cast<const float4*>(centers + (size_t)c * DIMS);
    float* __restrict__ oc = out_centers + (size_t)c * DIMS;

    if (last >= 0) {
        const float4* __restrict__ xr = reinterpret_cast<const float4*>(x + (size_t)last * DIMS);
        const float beta = 1.0f - ALPHA_F;
#pragma unroll
        for (int i = 0; i < 2; ++i) {
            const int idx  = threadIdx.x + i * 256;
            const float4 cv = cr[idx];
            const float4 xv = xr[idx];
            const int base = idx * 4;
            oc[base + 0] = ALPHA_F * cv.x + beta * xv.x;
            oc[base + 1] = ALPHA_F * cv.y + beta * xv.y;
            oc[base + 2] = ALPHA_F * cv.z + beta * xv.z;
            oc[base + 3] = ALPHA_F * cv.w + beta * xv.w;
        }
    } else {
#pragma unroll
        for (int i = 0; i < 2; ++i) {
            const int idx  = threadIdx.x + i * 256;
            const float4 cv = cr[idx];
            const int base = idx * 4;
            oc[base + 0] = cv.x;
            oc[base + 1] = cv.y;
            oc[base + 2] = cv.z;
            oc[base + 3] = cv.w;
        }
    }

    if (c == 0 && threadIdx.x == 0 && out_loss != nullptr) {
        *out_loss = (float)(g_loss_accum / ((double)NSAMP * (double)HEADSZ));
    }
}

// ---------------------------------------------------------------------------
extern "C" void kernel_launch(void* const* d_in, const int* in_sizes, int n_in,
                              void* d_out, int out_size) {
    const float* x       = (const float*)d_in[0];
    const int*   labels  = (const int*)  d_in[1];
    const float* centers = (const float*)d_in[2];

    float* out = (float*)d_out;
    const int centers_elems = NUM_CLASS * DIMS;          // 2,048,000
    // Outputs are concatenated [loss, new_centers]; compute centers base from
    // out_size so this stays correct even if only centers are emitted.
    float* out_centers = out + (out_size - centers_elems);
    float* out_loss    = (out_size > centers_elems) ? out : nullptr;

    ema_init_kernel<<<(NUM_CLASS + 255) / 256, 256>>>();
    ema_loss_kernel<<<NSAMP, 256>>>(x, labels, centers);
    ema_update_kernel<<<NUM_CLASS, 256>>>(x, centers, out_loss, out_centers);
}

// round 2
// speedup vs baseline: 1.0060x; 1.0060x over previous
#include <cuda_runtime.h>
#include <cuda_bf16.h>
#include <cstddef>

#define NUM_CLASS 1000
#define DIMS      2048
#define HEADSZ    256
#define NSAMP     16384
#define ALPHA_F   0.999f

// Scratch (allocation-free rule: __device__ globals).
// g_last_idx stores (sample_index + 1); 0 means "no sample". Zero-init at load
// time is therefore a valid empty state, and the update kernel restores it
// after consuming each entry -> no init kernel needed, graph-replay safe.
__device__ int    g_last_idx[NUM_CLASS];   // zero-initialized
__device__ double g_loss_accum;            // zero-initialized

// ---------------------------------------------------------------------------
// Kernel 1: per-sample SSE vs gathered center row, fused last-index atomicMax.
// One block per sample; 256 threads x 2 float4 = 2048 floats.
// ---------------------------------------------------------------------------
__global__ __launch_bounds__(256) void ema_loss_kernel(
    const float* __restrict__ x,
    const int*   __restrict__ labels,
    const float* __restrict__ centers)
{
    const int n   = blockIdx.x;
    const int lab = labels[n];

    if (threadIdx.x == 0) {
        atomicMax(&g_last_idx[lab], n + 1);   // +1 encoding, 0 == empty
    }

    const float4* __restrict__ xr = reinterpret_cast<const float4*>(x + (size_t)n * DIMS);
    const float4* __restrict__ cr = reinterpret_cast<const float4*>(centers + (size_t)lab * DIMS);

    // Batch all 4 loads up front for max MLP.
    const float4 a0 = xr[threadIdx.x];
    const float4 a1 = xr[threadIdx.x + 256];
    const float4 b0 = cr[threadIdx.x];
    const float4 b1 = cr[threadIdx.x + 256];

    float s;
    {
        const float dx0 = a0.x - b0.x, dy0 = a0.y - b0.y, dz0 = a0.z - b0.z, dw0 = a0.w - b0.w;
        const float dx1 = a1.x - b1.x, dy1 = a1.y - b1.y, dz1 = a1.z - b1.z, dw1 = a1.w - b1.w;
        s = dx0 * dx0 + dy0 * dy0 + dz0 * dz0 + dw0 * dw0
          + dx1 * dx1 + dy1 * dy1 + dz1 * dz1 + dw1 * dw1;
    }

    // warp reduce
#pragma unroll
    for (int o = 16; o > 0; o >>= 1) s += __shfl_xor_sync(0xFFFFFFFFu, s, o);

    __shared__ float warp_s[8];
    if ((threadIdx.x & 31) == 0) warp_s[threadIdx.x >> 5] = s;
    __syncthreads();

    if (threadIdx.x < 8) {
        float v = warp_s[threadIdx.x];
#pragma unroll
        for (int o = 4; o > 0; o >>= 1) v += __shfl_xor_sync(0xFFu, v, o);
        if (threadIdx.x == 0) {
            atomicAdd(&g_loss_accum, (double)v);
        }
    }
}

// ---------------------------------------------------------------------------
// Kernel 2: EMA scatter update (last write wins) + loss finalize + scratch
// reset for the next graph replay. One block per class; 256 thr x 8 floats.
// Scalar stores: output centers base may be 4B-aligned only (loss slot first).
// ---------------------------------------------------------------------------
__global__ __launch_bounds__(256) void ema_update_kernel(
    const float* __restrict__ x,
    const float* __restrict__ centers,
    float*       __restrict__ out_loss,      // may be null
    float*       __restrict__ out_centers)
{
    const int c       = blockIdx.x;
    const int last_p1 = g_last_idx[c];

    const float4* __restrict__ cr = reinterpret_cast<const float4*>(centers + (size_t)c * DIMS);
    float* __restrict__ oc = out_centers + (size_t)c * DIMS;

    if (last_p1 > 0) {
        const float4* __restrict__ xr =
            reinterpret_cast<const float4*>(x + (size_t)(last_p1 - 1) * DIMS);
        const float beta = 1.0f - ALPHA_F;
#pragma unroll
        for (int i = 0; i < 2; ++i) {
            const int idx  = threadIdx.x + i * 256;
            const float4 cv = cr[idx];
            const float4 xv = xr[idx];
            const int base = idx * 4;
            oc[base + 0] = ALPHA_F * cv.x + beta * xv.x;
            oc[base + 1] = ALPHA_F * cv.y + beta * xv.y;
            oc[base + 2] = ALPHA_F * cv.z + beta * xv.z;
            oc[base + 3] = ALPHA_F * cv.w + beta * xv.w;
        }
    } else {
#pragma unroll
        for (int i = 0; i < 2; ++i) {
            const int idx  = threadIdx.x + i * 256;
            const float4 cv = cr[idx];
            const int base = idx * 4;
            oc[base + 0] = cv.x;
            oc[base + 1] = cv.y;
            oc[base + 2] = cv.z;
            oc[base + 3] = cv.w;
        }
    }

    // Self-reset scratch for next replay (this block is the only reader of
    // entry c, and stream order puts the next loss kernel after us).
    if (threadIdx.x == 0) {
        g_last_idx[c] = 0;
        if (c == 0) {
            if (out_loss != nullptr) {
                *out_loss = (float)(g_loss_accum / ((double)NSAMP * (double)HEADSZ));
            }
            g_loss_accum = 0.0;
        }
    }
}

// ---------------------------------------------------------------------------
extern "C" void kernel_launch(void* const* d_in, const int* in_sizes, int n_in,
                              void* d_out, int out_size) {
    const float* x       = (const float*)d_in[0];
    const int*   labels  = (const int*)  d_in[1];
    const float* centers = (const float*)d_in[2];

    float* out = (float*)d_out;
    const int centers_elems = NUM_CLASS * DIMS;          // 2,048,000
    float* out_centers = out + (out_size - centers_elems);
    float* out_loss    = (out_size > centers_elems) ? out : nullptr;

    ema_loss_kernel<<<NSAMP, 256>>>(x, labels, centers);
    ema_update_kernel<<<NUM_CLASS, 256>>>(x, centers, out_loss, out_centers);
}

// round 3
// speedup vs baseline: 1.0643x; 1.0580x over previous
#include <cuda_runtime.h>
#include <cuda_bf16.h>
#include <cstddef>

#define NUM_CLASS 1000
#define DIMS      2048
#define HEADSZ    256
#define NSAMP     16384
#define ALPHA_F   0.999f

#define SAMPLES_PER_BLOCK 2
#define NLOSS_BLOCKS (NSAMP / SAMPLES_PER_BLOCK)   // 8192

// Scratch (__device__ globals; zero-init is the valid empty state, and the
// kernels self-reset everything for the next graph replay).
__device__ int    g_last_idx[NUM_CLASS];   // stores sample_index+1; 0 = empty
__device__ double g_loss_accum;
__device__ int    g_ticket;

// ---------------------------------------------------------------------------
// Kernel A: last-write-wins index per class, from labels only (64 KB read).
// ---------------------------------------------------------------------------
__global__ __launch_bounds__(512) void ema_lastidx_kernel(
    const int* __restrict__ labels)
{
    const int n = blockIdx.x * 512 + threadIdx.x;
    if (n < NSAMP) {
        atomicMax(&g_last_idx[labels[n]], n + 1);
    }
}

// ---------------------------------------------------------------------------
// Kernel B (fused): blocks [0, NLOSS_BLOCKS) compute SSE for 2 samples each;
// blocks [NLOSS_BLOCKS, NLOSS_BLOCKS+NUM_CLASS) do the EMA scatter update.
// The last loss block to retire finalizes the loss into out[0].
// ---------------------------------------------------------------------------
__global__ __launch_bounds__(256) void ema_fused_kernel(
    const float* __restrict__ x,
    const int*   __restrict__ labels,
    const float* __restrict__ centers,
    float*       __restrict__ out_loss,      // may be null
    float*       __restrict__ out_centers)
{
    const int b = blockIdx.x;

    if (b < NLOSS_BLOCKS) {
        // ---------------- loss path: 2 samples per block ----------------
        const int n0 = b * 2;
        const int n1 = n0 + 1;
        const int lab0 = labels[n0];        // uniform per block, one sector
        const int lab1 = labels[n1];

        const float4* __restrict__ xr0 = reinterpret_cast<const float4*>(x + (size_t)n0 * DIMS);
        const float4* __restrict__ xr1 = reinterpret_cast<const float4*>(x + (size_t)n1 * DIMS);
        const float4* __restrict__ cr0 = reinterpret_cast<const float4*>(centers + (size_t)lab0 * DIMS);
        const float4* __restrict__ cr1 = reinterpret_cast<const float4*>(centers + (size_t)lab1 * DIMS);

        const int t = threadIdx.x;
        // Front-batch all 8 loads for max MLP.
        const float4 a0 = xr0[t];
        const float4 a1 = xr0[t + 256];
        const float4 a2 = xr1[t];
        const float4 a3 = xr1[t + 256];
        const float4 b0 = cr0[t];
        const float4 b1 = cr0[t + 256];
        const float4 b2 = cr1[t];
        const float4 b3 = cr1[t + 256];

        float s;
        {
            float d;
            s  = (d = a0.x - b0.x) * d; s += (d = a0.y - b0.y) * d;
            s += (d = a0.z - b0.z) * d; s += (d = a0.w - b0.w) * d;
            s += (d = a1.x - b1.x) * d; s += (d = a1.y - b1.y) * d;
            s += (d = a1.z - b1.z) * d; s += (d = a1.w - b1.w) * d;
            s += (d = a2.x - b2.x) * d; s += (d = a2.y - b2.y) * d;
            s += (d = a2.z - b2.z) * d; s += (d = a2.w - b2.w) * d;
            s += (d = a3.x - b3.x) * d; s += (d = a3.y - b3.y) * d;
            s += (d = a3.z - b3.z) * d; s += (d = a3.w - b3.w) * d;
        }

        // warp reduce
#pragma unroll
        for (int o = 16; o > 0; o >>= 1) s += __shfl_xor_sync(0xFFFFFFFFu, s, o);

        __shared__ float warp_s[8];
        if ((threadIdx.x & 31) == 0) warp_s[threadIdx.x >> 5] = s;
        __syncthreads();

        if (threadIdx.x == 0) {
            float v = warp_s[0] + warp_s[1] + warp_s[2] + warp_s[3]
                    + warp_s[4] + warp_s[5] + warp_s[6] + warp_s[7];
            atomicAdd(&g_loss_accum, (double)v);
            __threadfence();
            const int old = atomicAdd(&g_ticket, 1);
            if (old == NLOSS_BLOCKS - 1) {
                // last loss block: finalize + reset scratch for next replay
                if (out_loss != nullptr) {
                    *out_loss = (float)(g_loss_accum / ((double)NSAMP * (double)HEADSZ));
                }
                g_loss_accum = 0.0;
                g_ticket     = 0;
            }
        }
    } else {
        // ---------------- update path: one class per block ----------------
        const int c       = b - NLOSS_BLOCKS;
        const int last_p1 = g_last_idx[c];   // final: kernel A completed

        const float4* __restrict__ cr = reinterpret_cast<const float4*>(centers + (size_t)c * DIMS);
        float* __restrict__ oc = out_centers + (size_t)c * DIMS;
        const int t = threadIdx.x;

        if (last_p1 > 0) {
            const float4* __restrict__ xr =
                reinterpret_cast<const float4*>(x + (size_t)(last_p1 - 1) * DIMS);
            const float beta = 1.0f - ALPHA_F;
            const float4 cv0 = cr[t];
            const float4 cv1 = cr[t + 256];
            const float4 xv0 = xr[t];
            const float4 xv1 = xr[t + 256];
            int base = t * 4;
            oc[base + 0] = ALPHA_F * cv0.x + beta * xv0.x;
            oc[base + 1] = ALPHA_F * cv0.y + beta * xv0.y;
            oc[base + 2] = ALPHA_F * cv0.z + beta * xv0.z;
            oc[base + 3] = ALPHA_F * cv0.w + beta * xv0.w;
            base += 1024;
            oc[base + 0] = ALPHA_F * cv1.x + beta * xv1.x;
            oc[base + 1] = ALPHA_F * cv1.y + beta * xv1.y;
            oc[base + 2] = ALPHA_F * cv1.z + beta * xv1.z;
            oc[base + 3] = ALPHA_F * cv1.w + beta * xv1.w;
        } else {
            const float4 cv0 = cr[t];
            const float4 cv1 = cr[t + 256];
            int base = t * 4;
            oc[base + 0] = cv0.x; oc[base + 1] = cv0.y;
            oc[base + 2] = cv0.z; oc[base + 3] = cv0.w;
            base += 1024;
            oc[base + 0] = cv1.x; oc[base + 1] = cv1.y;
            oc[base + 2] = cv1.z; oc[base + 3] = cv1.w;
        }

        // Self-reset for next replay (all threads already consumed last_p1
        // from their own uniform load before this point; sync then reset).
        __syncthreads();
        if (threadIdx.x == 0) {
            g_last_idx[c] = 0;
        }
    }
}

// ---------------------------------------------------------------------------
extern "C" void kernel_launch(void* const* d_in, const int* in_sizes, int n_in,
                              void* d_out, int out_size) {
    const float* x       = (const float*)d_in[0];
    const int*   labels  = (const int*)  d_in[1];
    const float* centers = (const float*)d_in[2];

    float* out = (float*)d_out;
    const int centers_elems = NUM_CLASS * DIMS;          // 2,048,000
    float* out_centers = out + (out_size - centers_elems);
    float* out_loss    = (out_size > centers_elems) ? out : nullptr;

    ema_lastidx_kernel<<<(NSAMP + 511) / 512, 512>>>(labels);
    ema_fused_kernel<<<NLOSS_BLOCKS + NUM_CLASS, 256>>>(x, labels, centers,
                                                        out_loss, out_centers);
}